// round 12
// baseline (speedup 1.0000x reference)
#include <cuda_runtime.h>
#include <cuda_bf16.h>
#include <cstddef>
#include <cstdint>

#define Bq   128
#define Tq   64
#define Hq   512
#define Vq   10000
#define Gq   2048            // 4*H
#define BTq  (Bq*Tq)         // 8192
#define NBLK 79              // ceil(V/128)
#define KS0  2               // layer0 K-splits (K=512 -> 256 each)
#define KS1  4               // layer1 K-splits (K=1024 -> 256 each)

// ---------------- scratch ----------------
__device__ float g_xw0[(size_t)BTq * Gq];       // TRANSPOSED: [t][gatecol][b]
__device__ float g_out[(size_t)BTq * Hq];
__device__ float g_pm[(size_t)BTq * NBLK];
__device__ float g_ps[(size_t)BTq * NBLK];
__device__ float g_zl[BTq];
__device__ float g_xent[BTq];
__device__ float g_h0[2][Bq * Hq];              // row-major [b][j]
__device__ float g_h1[2][Bq * Hq];
__device__ float g_c0[Bq * Hq];                 // TRANSPOSED [j][b]
__device__ float g_c1[Bq * Hq];                 // TRANSPOSED [j][b]
__device__ float g_o0[2][Bq * Hq];              // row-major, dbl-buffered by t parity
__device__ float g_p0[KS0][(size_t)Gq * Bq];    // L0 gate partials [split][col][row]
__device__ float g_p1[KS1][(size_t)Gq * Bq];    // L1 gate partials
__device__ unsigned g_cnt0[128];
__device__ unsigned g_cnt1[128];

__device__ __forceinline__ float sigf(float x) { return 1.f / (1.f + expf(-x)); }

__device__ __forceinline__ uint32_t s2u(const void* p) {
    return (uint32_t)__cvta_generic_to_shared(p);
}
__device__ __forceinline__ void cpa16(uint32_t dst, const void* src) {
    asm volatile("cp.async.cg.shared.global [%0], [%1], 16;" :: "r"(dst), "l"(src));
}
__device__ __forceinline__ void cpa16p(uint32_t dst, const void* src, bool pred) {
    int sz = pred ? 16 : 0;
    asm volatile("cp.async.cg.shared.global [%0], [%1], 16, %2;" :: "r"(dst), "l"(src), "r"(sz));
}
#define CP_COMMIT asm volatile("cp.async.commit_group;")
#define CP_WAIT1  asm volatile("cp.async.wait_group 1;")
#define CP_WAIT2  asm volatile("cp.async.wait_group 2;")

__device__ __forceinline__ void mma_tf32(float& d0, float& d1, float& d2, float& d3,
                                         unsigned a0, unsigned a1, unsigned a2, unsigned a3,
                                         unsigned b0, unsigned b1) {
    asm volatile(
        "mma.sync.aligned.m16n8k8.row.col.f32.tf32.tf32.f32 "
        "{%0,%1,%2,%3}, {%4,%5,%6,%7}, {%8,%9}, {%0,%1,%2,%3};"
        : "+f"(d0), "+f"(d1), "+f"(d2), "+f"(d3)
        : "r"(a0), "r"(a1), "r"(a2), "r"(a3), "r"(b0), "r"(b1));
}

// ---------------- init ----------------
__global__ void k_init() {
    int i = blockIdx.x * blockDim.x + threadIdx.x;
    if (i < Bq * Hq) {
        g_h0[0][i] = 0.f; g_c0[i] = 0.f;
        g_h1[0][i] = 0.f; g_c1[i] = 0.f;
    }
    if (i < 128) { g_cnt0[i] = 0u; g_cnt1[i] = 0u; }
}

// =======================================================================
// big tf32 GEMMs: block 128x128, warp 32x64, k-chunk 16, 2-stage cp.async
// =======================================================================
#define ASTR 20
#define BSTR 136

__global__ void k_xw0_tf32(const float* __restrict__ emb, const int* __restrict__ feat,
                           const float* __restrict__ Bm, const float* __restrict__ bias) {
    const int N = Gq, K = Hq;
    __shared__ float As[2][128 * ASTR];
    __shared__ float Bs[2][16 * BSTR];
    const int tid = threadIdx.x;
    const int bx = blockIdx.x, by = blockIdx.y;
    const int warp = tid >> 5, lane = tid & 31;
    const int wm = warp & 3, wn = warp >> 2;
    const int gID = lane >> 2, tig = lane & 3;

    const int arow = tid >> 2;
    const int aq   = (tid & 3) * 4;
    const float* asrc0 = emb + (size_t)feat[by * 128 + arow] * K + aq;
    const float* asrc1 = emb + (size_t)feat[by * 128 + arow + 64] * K + aq;
    const int bk = tid >> 5, bq = tid & 31;
    const float* bsrc = Bm + (size_t)bk * N + bx * 128 + bq * 4;

    float acc[2][8][4];
#pragma unroll
    for (int mt = 0; mt < 2; ++mt)
#pragma unroll
        for (int nt = 0; nt < 8; ++nt)
#pragma unroll
            for (int e = 0; e < 4; ++e) acc[mt][nt][e] = 0.f;

    const int NC = K / 16;
    {
        cpa16(s2u(&As[0][arow * ASTR + aq]), asrc0);
        cpa16(s2u(&As[0][(arow + 64) * ASTR + aq]), asrc1);
        cpa16(s2u(&Bs[0][bk * BSTR + bq * 4]), bsrc);
        cpa16(s2u(&Bs[0][(bk + 8) * BSTR + bq * 4]), bsrc + (size_t)8 * N);
    }
    CP_COMMIT;
    for (int c = 0; c < NC; ++c) {
        const int cur = c & 1, nxt = cur ^ 1;
        if (c + 1 < NC) {
            int k0 = (c + 1) * 16;
            cpa16(s2u(&As[nxt][arow * ASTR + aq]), asrc0 + k0);
            cpa16(s2u(&As[nxt][(arow + 64) * ASTR + aq]), asrc1 + k0);
            cpa16(s2u(&Bs[nxt][bk * BSTR + bq * 4]), bsrc + (size_t)k0 * N);
            cpa16(s2u(&Bs[nxt][(bk + 8) * BSTR + bq * 4]), bsrc + (size_t)(k0 + 8) * N);
        }
        CP_COMMIT;
        CP_WAIT1;
        __syncthreads();
        const unsigned* Au = (const unsigned*)As[cur];
        const unsigned* Bu = (const unsigned*)Bs[cur];
#pragma unroll
        for (int ks = 0; ks < 2; ++ks) {
            unsigned a[2][4];
#pragma unroll
            for (int mt = 0; mt < 2; ++mt) {
                int mr = wm * 32 + mt * 16;
                a[mt][0] = Au[(mr + gID    ) * ASTR + ks * 8 + tig];
                a[mt][1] = Au[(mr + gID + 8) * ASTR + ks * 8 + tig];
                a[mt][2] = Au[(mr + gID    ) * ASTR + ks * 8 + tig + 4];
                a[mt][3] = Au[(mr + gID + 8) * ASTR + ks * 8 + tig + 4];
            }
#pragma unroll
            for (int nt = 0; nt < 8; ++nt) {
                int nc = wn * 64 + nt * 8 + gID;
                unsigned b0 = Bu[(ks * 8 + tig    ) * BSTR + nc];
                unsigned b1 = Bu[(ks * 8 + tig + 4) * BSTR + nc];
#pragma unroll
                for (int mt = 0; mt < 2; ++mt)
                    mma_tf32(acc[mt][nt][0], acc[mt][nt][1], acc[mt][nt][2], acc[mt][nt][3],
                             a[mt][0], a[mt][1], a[mt][2], a[mt][3], b0, b1);
            }
        }
        __syncthreads();
    }
    // epilogue: bias + TRANSPOSED store g_xw0[t][gatecol][b]
#pragma unroll
    for (int mt = 0; mt < 2; ++mt) {
#pragma unroll
        for (int er = 0; er < 2; ++er) {
            int gm = by * 128 + wm * 32 + mt * 16 + gID + er * 8;
            int b_ = gm >> 6, t_ = gm & 63;
#pragma unroll
            for (int nt = 0; nt < 8; ++nt) {
#pragma unroll
                for (int e = 0; e < 2; ++e) {
                    int gn = bx * 128 + wn * 64 + nt * 8 + tig * 2 + e;
                    g_xw0[((size_t)t_ * Gq + gn) * Bq + b_] =
                        acc[mt][nt][er * 2 + e] + bias[gn];
                }
            }
        }
    }
}

__global__ void k_logits_tf32(const float* __restrict__ Bm,
                              const float* __restrict__ bias,
                              const int* __restrict__ labels) {
    const int N = Vq, K = Hq;
    __shared__ float As[2][128 * ASTR];
    __shared__ float Bs[2][16 * BSTR];
    __shared__ float pm[128][9];
    __shared__ float ps[128][9];
    const int tid = threadIdx.x;
    const int bx = blockIdx.x, by = blockIdx.y;
    const int warp = tid >> 5, lane = tid & 31;
    const int wm = warp & 3, wn = warp >> 2;
    const int gID = lane >> 2, tig = lane & 3;

    const int arow = tid >> 2;
    const int aq   = (tid & 3) * 4;
    const float* asrc0 = g_out + (size_t)(by * 128 + arow) * K + aq;
    const float* asrc1 = asrc0 + (size_t)64 * K;
    const int bk = tid >> 5, bq = tid & 31;
    const int gnq = bx * 128 + bq * 4;
    const bool bpred = (gnq + 3 < N);
    const float* bsrc = Bm + (size_t)bk * N + (bpred ? gnq : 0);

    float acc[2][8][4];
#pragma unroll
    for (int mt = 0; mt < 2; ++mt)
#pragma unroll
        for (int nt = 0; nt < 8; ++nt)
#pragma unroll
            for (int e = 0; e < 4; ++e) acc[mt][nt][e] = 0.f;

    const int NC = K / 16;
    {
        cpa16(s2u(&As[0][arow * ASTR + aq]), asrc0);
        cpa16(s2u(&As[0][(arow + 64) * ASTR + aq]), asrc1);
        cpa16p(s2u(&Bs[0][bk * BSTR + bq * 4]), bsrc, bpred);
        cpa16p(s2u(&Bs[0][(bk + 8) * BSTR + bq * 4]), bsrc + (size_t)8 * N, bpred);
    }
    CP_COMMIT;
    for (int c = 0; c < NC; ++c) {
        const int cur = c & 1, nxt = cur ^ 1;
        if (c + 1 < NC) {
            int k0 = (c + 1) * 16;
            cpa16(s2u(&As[nxt][arow * ASTR + aq]), asrc0 + k0);
            cpa16(s2u(&As[nxt][(arow + 64) * ASTR + aq]), asrc1 + k0);
            cpa16p(s2u(&Bs[nxt][bk * BSTR + bq * 4]), bsrc + (size_t)k0 * N, bpred);
            cpa16p(s2u(&Bs[nxt][(bk + 8) * BSTR + bq * 4]), bsrc + (size_t)(k0 + 8) * N, bpred);
        }
        CP_COMMIT;
        CP_WAIT1;
        __syncthreads();
        const unsigned* Au = (const unsigned*)As[cur];
        const unsigned* Bu = (const unsigned*)Bs[cur];
#pragma unroll
        for (int ks = 0; ks < 2; ++ks) {
            unsigned a[2][4];
#pragma unroll
            for (int mt = 0; mt < 2; ++mt) {
                int mr = wm * 32 + mt * 16;
                a[mt][0] = Au[(mr + gID    ) * ASTR + ks * 8 + tig];
                a[mt][1] = Au[(mr + gID + 8) * ASTR + ks * 8 + tig];
                a[mt][2] = Au[(mr + gID    ) * ASTR + ks * 8 + tig + 4];
                a[mt][3] = Au[(mr + gID + 8) * ASTR + ks * 8 + tig + 4];
            }
#pragma unroll
            for (int nt = 0; nt < 8; ++nt) {
                int nc = wn * 64 + nt * 8 + gID;
                unsigned b0 = Bu[(ks * 8 + tig    ) * BSTR + nc];
                unsigned b1 = Bu[(ks * 8 + tig + 4) * BSTR + nc];
#pragma unroll
                for (int mt = 0; mt < 2; ++mt)
                    mma_tf32(acc[mt][nt][0], acc[mt][nt][1], acc[mt][nt][2], acc[mt][nt][3],
                             a[mt][0], a[mt][1], a[mt][2], a[mt][3], b0, b1);
            }
        }
        __syncthreads();
    }

#pragma unroll
    for (int mt = 0; mt < 2; ++mt) {
#pragma unroll
        for (int er = 0; er < 2; ++er) {
            int lr = wm * 32 + mt * 16 + gID + er * 8;
            int gm = by * 128 + lr;
            int lab = labels[gm];
            float lm = -1e30f, lsum = 0.f;
            float v[16];
#pragma unroll
            for (int nt = 0; nt < 8; ++nt) {
#pragma unroll
                for (int e = 0; e < 2; ++e) {
                    int gn = bx * 128 + wn * 64 + nt * 8 + tig * 2 + e;
                    float cc = acc[mt][nt][er * 2 + e];
                    if (gn < N) {
                        float z = cc + bias[gn];
                        v[nt * 2 + e] = z;
                        if (gn == lab) g_zl[gm] = z;
                        lm = fmaxf(lm, z);
                    } else v[nt * 2 + e] = -1e30f;
                }
            }
#pragma unroll
            for (int q = 0; q < 16; ++q) lsum += expf(v[q] - lm);
            if (lm <= -1e30f) lsum = 0.f;
            pm[lr][wn * 4 + tig] = lm;
            ps[lr][wn * 4 + tig] = lsum;
        }
    }
    __syncthreads();
    if (tid < 128) {
        float m = -1e30f, s = 0.f;
#pragma unroll
        for (int x = 0; x < 8; ++x) {
            float m2 = pm[tid][x], s2 = ps[tid][x];
            float M = fmaxf(m, m2);
            s = s * expf(m - M) + s2 * expf(m2 - M);
            m = M;
        }
        int gm = by * 128 + tid;
        g_pm[(size_t)gm * NBLK + bx] = m;
        g_ps[(size_t)gm * NBLK + bx] = s;
    }
}

// =======================================================================
// split-K LSTM steps: each block = 16 k-chunks of one (jblk, split);
// partials -> global; last-arriving block reduces + cell update.
// SMEM: 3 stages x (A[128][20]+B[16][24]) = 34.5 KB.
// =======================================================================
#define SA  20
#define SB  24
#define NSTG 3

// 16-chunk MMA over A[:, kbase..kbase+256) x W[kbase.., j0 cols]
__device__ __forceinline__ void run_split(
        const float* __restrict__ A, const float* __restrict__ W,
        int kbase, int j0, float* Asm, float* Bsm,
        int tid, int wm, int gID, int tig, float acc[2][4]) {
    const int ar = tid >> 1, aq = (tid & 1) * 8;
    const int bk = tid >> 2, bg = tid & 3;          // tid<64 fills B
    const int NC = 16;

    auto issue = [&](int cc) {
        int k0 = kbase + cc * 16;
        float* Ab = Asm + (cc % NSTG) * (128 * SA);
        float* Bb = Bsm + (cc % NSTG) * (16 * SB);
        cpa16(s2u(&Ab[ar * SA + aq]),     A + (size_t)ar * Hq + k0 + aq);
        cpa16(s2u(&Ab[ar * SA + aq + 4]), A + (size_t)ar * Hq + k0 + aq + 4);
        if (tid < 64)
            cpa16(s2u(&Bb[bk * SB + bg * 4]),
                  W + (size_t)(k0 + bk) * Gq + bg * Hq + j0);
    };

    issue(0); CP_COMMIT;
    issue(1); CP_COMMIT;
    for (int c = 0; c < NC; ++c) {
        if (c + 2 < NC) issue(c + 2);
        CP_COMMIT;                 // unconditional: group index == chunk index
        CP_WAIT2;                  // chunk c retired
        __syncthreads();
        const unsigned* Au = (const unsigned*)(Asm + (c % NSTG) * (128 * SA));
        const unsigned* Bu = (const unsigned*)(Bsm + (c % NSTG) * (16 * SB));
#pragma unroll
        for (int ks = 0; ks < 2; ++ks) {
            unsigned a0 = Au[(wm * 16 + gID    ) * SA + ks * 8 + tig];
            unsigned a1 = Au[(wm * 16 + gID + 8) * SA + ks * 8 + tig];
            unsigned a2 = Au[(wm * 16 + gID    ) * SA + ks * 8 + tig + 4];
            unsigned a3 = Au[(wm * 16 + gID + 8) * SA + ks * 8 + tig + 4];
#pragma unroll
            for (int nt = 0; nt < 2; ++nt) {
                int n = nt * 8 + gID;
                unsigned b0 = Bu[(ks * 8 + tig    ) * SB + n];
                unsigned b1 = Bu[(ks * 8 + tig + 4) * SB + n];
                mma_tf32(acc[nt][0], acc[nt][1], acc[nt][2], acc[nt][3],
                         a0, a1, a2, a3, b0, b1);
            }
        }
        __syncthreads();
    }
}

__device__ __forceinline__ void stage_accs(float* stg, int wm, int gID, int tig,
                                           float acc[2][4]) {
#pragma unroll
    for (int nt = 0; nt < 2; ++nt)
#pragma unroll
        for (int er = 0; er < 2; ++er)
#pragma unroll
            for (int e = 0; e < 2; ++e)
                stg[(wm * 16 + gID + er * 8) * 17 + nt * 8 + tig * 2 + e] =
                    acc[nt][er * 2 + e];
}

// write staged gate tile -> partial [col][row] (coalesced)
__device__ __forceinline__ void write_partial(const float* stg, float* gp,
                                              int jblk, int tid) {
    int col = tid >> 4, r0 = (tid & 15) * 8;
    float v[8];
#pragma unroll
    for (int rr = 0; rr < 8; ++rr) v[rr] = stg[(r0 + rr) * 17 + col];
    float* dst = gp + ((size_t)(jblk * 16 + col)) * Bq + r0;
    *(float4*)dst       = make_float4(v[0], v[1], v[2], v[3]);
    *(float4*)(dst + 4) = make_float4(v[4], v[5], v[6], v[7]);
}

// generic: true iff this block is the last arriver for its group
__device__ __forceinline__ bool arrive_last(unsigned* cnt, int ks, int tid, int* flag) {
    __threadfence();
    __syncthreads();
    if (tid == 0) {
        unsigned old = atomicAdd(cnt, 1u);
        *flag = (old == (unsigned)(ks - 1));
        if (*flag) *cnt = 0u;       // reset for next launch
    }
    __syncthreads();
    bool w = (*flag != 0);
    if (w) __threadfence();
    return w;
}

// ---- layer 0 split block ----
__device__ void layer0_split(int t, int jblk, int split,
                             const int* __restrict__ seq_len,
                             const float* __restrict__ W0h,
                             float* Asm, float* Bsm, int* flag) {
    const int tid = threadIdx.x, lane = tid & 31, wm = tid >> 5;
    const int gID = lane >> 2, tig = lane & 3;
    const int j0 = jblk * 4;
    const int rb = t & 1, wb = rb ^ 1;
    const float* __restrict__ hbuf = g_h0[rb];

    float acc[2][4] = {};
    run_split(hbuf, W0h, split * 256, j0, Asm, Bsm, tid, wm, gID, tig, acc);

    stage_accs(Asm, wm, gID, tig, acc);
    __syncthreads();
    write_partial(Asm, g_p0[split], jblk, tid);

    if (!arrive_last(&g_cnt0[jblk], KS0, tid, flag)) return;

    // reducer: sum partials + xw0, cell update
#pragma unroll
    for (int i = 0; i < 2; ++i) {
        int cell = i * 256 + tid;
        int row = cell & 127, jl = cell >> 7;
        int j = j0 + jl;
        float gs[4];
#pragma unroll
        for (int g = 0; g < 4; ++g) {
            float v = 0.f;
#pragma unroll
            for (int s = 0; s < KS0; ++s)
                v += g_p0[s][((size_t)(jblk * 16 + g * 4 + jl)) * Bq + row];
            v += g_xw0[((size_t)t * Gq + g * Hq + j) * Bq + row];
            gs[g] = v;
        }
        bool m = t < seq_len[row];
        int sc = j * Bq + row;        // transposed c
        int sh = row * Hq + j;        // row-major h
        float cold = g_c0[sc], hold = hbuf[sh];
        float cn = sigf(gs[2]) * cold + sigf(gs[0]) * tanhf(gs[1]);
        float hn = sigf(gs[3]) * tanhf(cn);
        g_c0[sc]       = m ? cn : cold;
        g_h0[wb][sh]   = m ? hn : hold;
        g_o0[t & 1][sh]= m ? hn : 0.f;
    }
}

// ---- layer 1 split block: splits 0,1 -> o0@W1x; 2,3 -> h1@W1h ----
__device__ void layer1_split(int t, int jblk, int split,
                             const int* __restrict__ seq_len,
                             const float* __restrict__ W1x,
                             const float* __restrict__ W1h,
                             const float* __restrict__ b1,
                             float* Asm, float* Bsm, int* flag) {
    const int tid = threadIdx.x, lane = tid & 31, wm = tid >> 5;
    const int gID = lane >> 2, tig = lane & 3;
    const int j0 = jblk * 4;
    const int rb = t & 1, wb = rb ^ 1;
    const float* __restrict__ h1buf = g_h1[rb];

    const float* A = (split < 2) ? g_o0[t & 1] : h1buf;
    const float* W = (split < 2) ? W1x : W1h;
    int kbase = (split & 1) * 256;

    float acc[2][4] = {};
    run_split(A, W, kbase, j0, Asm, Bsm, tid, wm, gID, tig, acc);

    stage_accs(Asm, wm, gID, tig, acc);
    __syncthreads();
    write_partial(Asm, g_p1[split], jblk, tid);

    if (!arrive_last(&g_cnt1[jblk], KS1, tid, flag)) return;

#pragma unroll
    for (int i = 0; i < 2; ++i) {
        int cell = i * 256 + tid;
        int row = cell & 127, jl = cell >> 7;
        int j = j0 + jl;
        float gs[4];
#pragma unroll
        for (int g = 0; g < 4; ++g) {
            float v = 0.f;
#pragma unroll
            for (int s = 0; s < KS1; ++s)
                v += g_p1[s][((size_t)(jblk * 16 + g * 4 + jl)) * Bq + row];
            v += b1[g * Hq + j];
            gs[g] = v;
        }
        bool m = t < seq_len[row];
        int sc = j * Bq + row;
        int sh = row * Hq + j;
        float cold = g_c1[sc], hold = h1buf[sh];
        float cn = sigf(gs[2]) * cold + sigf(gs[0]) * tanhf(gs[1]);
        float hn = sigf(gs[3]) * tanhf(cn);
        g_c1[sc]     = m ? cn : cold;
        g_h1[wb][sh] = m ? hn : hold;
        g_out[((size_t)row * Tq + t) * Hq + j] = m ? hn : 0.f;
    }
}

__global__ void __launch_bounds__(256) lstm_l0_only(const int* __restrict__ seq_len,
                                                    const float* __restrict__ W0h, int t) {
    __shared__ float Asm[NSTG][128 * SA];
    __shared__ float Bsm[NSTG][16 * SB];
    __shared__ int flag;
    layer0_split(t, blockIdx.x >> 1, blockIdx.x & 1, seq_len, W0h,
                 &Asm[0][0], &Bsm[0][0], &flag);
}

__global__ void __launch_bounds__(256) lstm_l1_only(const int* __restrict__ seq_len,
                                                    const float* __restrict__ W1x,
                                                    const float* __restrict__ W1h,
                                                    const float* __restrict__ b1, int t) {
    __shared__ float Asm[NSTG][128 * SA];
    __shared__ float Bsm[NSTG][16 * SB];
    __shared__ int flag;
    layer1_split(t, blockIdx.x >> 2, blockIdx.x & 3, seq_len, W1x, W1h, b1,
                 &Asm[0][0], &Bsm[0][0], &flag);
}

// fused: blocks 0-511 -> layer1(t) splits;  512-767 -> layer0(t+1) splits
__global__ void __launch_bounds__(256) lstm_fused(const int* __restrict__ seq_len,
                                                  const float* __restrict__ W0h,
                                                  const float* __restrict__ W1x,
                                                  const float* __restrict__ W1h,
                                                  const float* __restrict__ b1, int t) {
    __shared__ float Asm[NSTG][128 * SA];
    __shared__ float Bsm[NSTG][16 * SB];
    __shared__ int flag;
    if (blockIdx.x < 512)
        layer1_split(t, blockIdx.x >> 2, blockIdx.x & 3, seq_len, W1x, W1h, b1,
                     &Asm[0][0], &Bsm[0][0], &flag);
    else {
        int idx = blockIdx.x - 512;
        layer0_split(t + 1, idx >> 1, idx & 1, seq_len, W0h,
                     &Asm[0][0], &Bsm[0][0], &flag);
    }
}

// ---------------- partial softmax merge; xent ----------------
__global__ void k_xent_reduce() {
    const int row  = blockIdx.x * 8 + (threadIdx.x >> 5);
    const int lane = threadIdx.x & 31;
    float m = -1e30f, s = 0.f;
    for (int p = lane; p < NBLK; p += 32) {
        float m2 = g_pm[(size_t)row * NBLK + p];
        float s2 = g_ps[(size_t)row * NBLK + p];
        float M = fmaxf(m, m2);
        s = s * expf(m - M) + s2 * expf(m2 - M);
        m = M;
    }
#pragma unroll
    for (int o = 16; o > 0; o >>= 1) {
        float m2 = __shfl_xor_sync(0xffffffff, m, o);
        float s2 = __shfl_xor_sync(0xffffffff, s, o);
        float M = fmaxf(m, m2);
        s = s * expf(m - M) + s2 * expf(m2 - M);
        m = M;
    }
    if (lane == 0) g_xent[row] = -(g_zl[row] - m - logf(s));
}

// ---------------- final masked reduction ----------------
__global__ void k_loss(const float* __restrict__ seq_mask, float* __restrict__ out) {
    const int t = threadIdx.x;
    float sx = 0.f, sw_ = 0.f;
    for (int b = 0; b < Bq; ++b) {
        int i = b * Tq + t;
        float w = seq_mask[i];
        sx  += g_xent[i] * w;
        sw_ += w;
    }
    __shared__ float sh[64];
    sh[t] = sx / (sw_ + 1e-12f);
    __syncthreads();
    for (int o = 32; o > 0; o >>= 1) { if (t < o) sh[t] += sh[t + o]; __syncthreads(); }
    if (t == 0) out[0] = sh[0] / Tq;
}

// ---------------- launch ----------------
extern "C" void kernel_launch(void* const* d_in, const int* in_sizes, int n_in,
                              void* d_out, int out_size) {
    const int*   features = (const int*)  d_in[0];
    const int*   labels   = (const int*)  d_in[1];
    const int*   seq_len  = (const int*)  d_in[2];
    const float* seq_mask = (const float*)d_in[3];
    const float* emb      = (const float*)d_in[4];
    const float* W0x      = (const float*)d_in[5];
    const float* W0h      = (const float*)d_in[6];
    const float* b0       = (const float*)d_in[7];
    const float* W1x      = (const float*)d_in[8];
    const float* W1h      = (const float*)d_in[9];
    const float* b1       = (const float*)d_in[10];
    const float* smw      = (const float*)d_in[11];
    const float* smb      = (const float*)d_in[12];
    float* out = (float*)d_out;

    k_init<<<(Bq * Hq + 255) / 256, 256>>>();

    k_xw0_tf32<<<dim3(Gq / 128, BTq / 128), 256>>>(emb, features, W0x, b0);

    // split-K software-pipelined recurrence
    lstm_l0_only<<<128 * KS0, 256>>>(seq_len, W0h, 0);
    for (int t = 0; t < Tq - 1; ++t)
        lstm_fused<<<128 * (KS0 + KS1), 256>>>(seq_len, W0h, W1x, W1h, b1, t);
    lstm_l1_only<<<128 * KS1, 256>>>(seq_len, W1x, W1h, b1, Tq - 1);

    k_logits_tf32<<<dim3(NBLK, BTq / 128), 256>>>(smw, smb, labels);
    k_xent_reduce<<<BTq / 8, 256>>>();
    k_loss<<<1, 64>>>(seq_mask, out);
}